// round 11
// baseline (speedup 1.0000x reference)
#include <cuda_runtime.h>

#define NN0 100000
#define NN1 25000
#define NN2 6250
#define EE0 600000
#define EE1 150000
#define EE2 37500
#define ED0 100000
#define ED1 25000

// concatenated count bases: [g0][g1][g2][D0 rows][D1 rows]
#define CB0 0
#define CB1 NN0
#define CB2 (NN0 + NN1)
#define CBD0 (NN0 + NN1 + NN2)
#define CBD1 (CBD0 + NN1)
#define CNT_TOT (CBD1 + NN2)                 // 162500
#define ETOT_ALL (EE0 + EE1 + EE2 + ED0 + ED1)  // 912500
#define SCAN_BLK 1024
#define NSCAN_BLKS ((CNT_TOT + SCAN_BLK - 1) / SCAN_BLK)  // 159

// ---------------- scratch (device globals; no allocations allowed) ----------
__device__ __align__(16) float g_dinv0[NN0], g_dinv1[NN1], g_dinv2[NN2];
__device__ __align__(16) int g_cnt[CNT_TOT];
__device__ __align__(16) int g_rowptr[CNT_TOT];
__device__ __align__(16) int g_fill[CNT_TOT];
__device__ __align__(16) int g_bsum[NSCAN_BLKS];
__device__ __align__(16) unsigned g_bars[4];
__device__ __align__(16) int2 g_epack[ETOT_ALL];   // (src, w bits)
__device__ __align__(16) float g_T0[(size_t)NN0 * 24];   // 6 planes of [NN0,4]
__device__ __align__(16) float g_T1[(size_t)NN1 * 768];
__device__ __align__(16) float g_h1[(size_t)NN1 * 128];
__device__ __align__(16) float g_T2[(size_t)NN2 * 768];
__device__ __align__(16) float g_h2[(size_t)NN2 * 256];

static inline int cdiv(int a, int b) { return (a + b - 1) / b; }

// ---------------- helpers ----------------------------------------------------
__device__ __forceinline__ float tf32r(float x) {
    unsigned u;
    asm("cvt.rna.tf32.f32 %0, %1;" : "=r"(u) : "f"(x));
    return __uint_as_float(u);
}

__device__ __forceinline__ void mma_tf32(float& c0, float& c1, float& c2, float& c3,
                                         unsigned a0, unsigned a1, unsigned a2, unsigned a3,
                                         unsigned b0, unsigned b1) {
    asm volatile(
        "mma.sync.aligned.m16n8k8.row.col.f32.tf32.tf32.f32 "
        "{%0,%1,%2,%3},{%4,%5,%6,%7},{%8,%9},{%0,%1,%2,%3};"
        : "+f"(c0), "+f"(c1), "+f"(c2), "+f"(c3)
        : "r"(a0), "r"(a1), "r"(a2), "r"(a3), "r"(b0), "r"(b1));
}

__device__ __forceinline__ void gbar(unsigned* bar, unsigned target) {
    __threadfence();
    __syncthreads();
    if (threadIdx.x == 0) {
        atomicAdd(bar, 1u);
        while (*((volatile unsigned*)bar) < target) {}
        __threadfence();
    }
    __syncthreads();
}

// ---------------- CSR build ---------------------------------------------------
__global__ void hist_k(const int* e0, const int* e1, const int* e2,
                       const int* d0r, const int* d1r,
                       float* dv0, float* dv1, float* dv2, int* __restrict__ cnt) {
    int i = blockIdx.x * blockDim.x + threadIdx.x;
    if (i < EE0) {
        atomicAdd(&dv0[e0[i]], 1.f);
        atomicAdd(&cnt[CB0 + e0[EE0 + i]], 1);
        return;
    }
    i -= EE0;
    if (i < EE1) {
        atomicAdd(&dv1[e1[i]], 1.f);
        atomicAdd(&cnt[CB1 + e1[EE1 + i]], 1);
        return;
    }
    i -= EE1;
    if (i < EE2) {
        atomicAdd(&dv2[e2[i]], 1.f);
        atomicAdd(&cnt[CB2 + e2[EE2 + i]], 1);
        return;
    }
    i -= EE2;
    if (i < ED0) { atomicAdd(&cnt[CBD0 + d0r[i]], 1); return; }
    i -= ED0;
    if (i < ED1) atomicAdd(&cnt[CBD1 + d1r[i]], 1);
}

// fused: dinv + per-block scan + cross-block prefix + rowptr/fill + out init
__global__ __launch_bounds__(1024, 2) void scanfused_k(
    const int* __restrict__ cnt, int* __restrict__ rowptr, int* __restrict__ fill,
    int* __restrict__ bsum, float* d0, float* d1, float* d2,
    const float* __restrict__ linb, float* __restrict__ out, unsigned* bar) {
    __shared__ int sm[SCAN_BLK];
    __shared__ int bsm[NSCAN_BLKS];
    __shared__ int boff_sh;
    int t = threadIdx.x;
    int gid = blockIdx.x * SCAN_BLK + t;

    if (gid < 10) out[gid] = linb[gid];

    if (gid < NN0) { float v = d0[gid]; d0[gid] = v > 0.f ? rsqrtf(v) : 0.f; }
    else {
        int j = gid - NN0;
        if (j < NN1) { float v = d1[j]; d1[j] = v > 0.f ? rsqrtf(v) : 0.f; }
        else {
            int k = j - NN1;
            if (k < NN2) { float v = d2[k]; d2[k] = v > 0.f ? rsqrtf(v) : 0.f; }
        }
    }

    int v = (gid < CNT_TOT) ? cnt[gid] : 0;
    sm[t] = v;
    __syncthreads();
    for (int off = 1; off < SCAN_BLK; off <<= 1) {
        int add = (t >= off) ? sm[t - off] : 0;
        __syncthreads();
        sm[t] += add;
        __syncthreads();
    }
    if (t == SCAN_BLK - 1) bsum[blockIdx.x] = sm[t];

    gbar(bar, gridDim.x);

    if (t < NSCAN_BLKS) bsm[t] = bsum[t];
    __syncthreads();
    if (t == 0) {
        int a = 0;
        for (int i = 0; i < (int)blockIdx.x; i++) a += bsm[i];
        boff_sh = a;
    }
    __syncthreads();
    if (gid < CNT_TOT) {
        int start = sm[t] - v + boff_sh;
        rowptr[gid] = start;
        fill[gid] = start;
    }
}

// fill CSR edge arrays (src, weight) grouped by dst; also init T0 plane 0
__global__ void fill_k(const int* e0, const int* e1, const int* e2,
                       const int* d0r, const int* d0c, const float* d0v,
                       const int* d1r, const int* d1c, const float* d1v,
                       const float* dv0, const float* dv1, const float* dv2,
                       int* __restrict__ fill, int2* __restrict__ ep,
                       const float* __restrict__ x, float* __restrict__ T0) {
    int i = blockIdx.x * blockDim.x + threadIdx.x;
    if (i < NN0)
        *(float4*)(T0 + (size_t)i * 4) =
            make_float4(x[3 * i], x[3 * i + 1], x[3 * i + 2], 0.f);
    int src, cb; float w;
    if (i < EE0) {
        src = e0[i]; int dst = e0[EE0 + i];
        w = -dv0[src] * dv0[dst]; cb = CB0 + dst;
    } else if ((i -= EE0) < EE1) {
        src = e1[i]; int dst = e1[EE1 + i];
        w = -dv1[src] * dv1[dst]; cb = CB1 + dst;
    } else if ((i -= EE1) < EE2) {
        src = e2[i]; int dst = e2[EE2 + i];
        w = -dv2[src] * dv2[dst]; cb = CB2 + dst;
    } else if ((i -= EE2) < ED0) {
        src = d0c[i]; w = d0v[i]; cb = CBD0 + d0r[i];
    } else if ((i -= ED0) < ED1) {
        src = d1c[i]; w = d1v[i]; cb = CBD1 + d1r[i];
    } else return;
    int pos = atomicAdd(&fill[cb], 1);
    ep[pos] = make_int2(src, __float_as_int(w));
}

// ---------------- layer-0 propagation: 4 threads per dst node ----------------
template <bool SUB>
__global__ void gather3q_k(const int* __restrict__ rowptr, const int* __restrict__ cnt,
                           const int2* __restrict__ ep, float* __restrict__ T,
                           float coef, int in_p, int out_p, int prev_p) {
    int gt = blockIdx.x * blockDim.x + threadIdx.x;
    int node = gt >> 2, q = gt & 3;
    bool valid = node < NN0;
    int nodec = valid ? node : 0;
    int s = rowptr[nodec];
    int n = valid ? cnt[nodec] : 0;
    const float* Tin = T + (size_t)in_p * NN0 * 4;
    float ax = 0.f, ay = 0.f, az = 0.f;
    for (int i = q; i < n; i += 4) {
        int2 p = ep[s + i];
        float w = __int_as_float(p.y);
        float4 xv = *(const float4*)(Tin + (size_t)p.x * 4);
        ax = fmaf(w, xv.x, ax); ay = fmaf(w, xv.y, ay); az = fmaf(w, xv.z, az);
    }
    // quad reduction (all lanes participate; full warp active)
    ax += __shfl_xor_sync(0xffffffffu, ax, 1);
    ay += __shfl_xor_sync(0xffffffffu, ay, 1);
    az += __shfl_xor_sync(0xffffffffu, az, 1);
    ax += __shfl_xor_sync(0xffffffffu, ax, 2);
    ay += __shfl_xor_sync(0xffffffffu, ay, 2);
    az += __shfl_xor_sync(0xffffffffu, az, 2);
    if (valid && q == 0) {
        float4 o;
        if (SUB) {
            float4 pr = *(const float4*)(T + ((size_t)prev_p * NN0 + node) * 4);
            o = make_float4(coef * ax - pr.x, coef * ay - pr.y, coef * az - pr.z, 0.f);
        } else {
            o = make_float4(coef * ax, coef * ay, coef * az, 0.f);
        }
        *(float4*)(T + ((size_t)out_p * NN0 + node) * 4) = o;
    }
}

// ---------------- fused gemm0(+relu) + pool0 ---------------------------------
__global__ void __launch_bounds__(256) poolgemm0_k(const int* __restrict__ rowptr,
                                                   const int* __restrict__ cnt,
                                                   const int2* __restrict__ ep,
                                                   const float* __restrict__ T0,
                                                   const float* __restrict__ W,
                                                   const float* __restrict__ bias,
                                                   float* __restrict__ T1) {
    __shared__ float Ws[18 * 128];
    int tid = threadIdx.x;
    for (int i = tid; i < 18 * 128; i += 256) Ws[i] = W[i];
    __syncthreads();
    int lane = tid & 31;
    int warp = (blockIdx.x * 256 + tid) >> 5;
    if (warp >= NN1) return;
    int c0 = lane * 4;
    float4 b4 = *(const float4*)(bias + c0);
    int s = rowptr[CBD0 + warp], n = cnt[CBD0 + warp];
    float4 acc = make_float4(0.f, 0.f, 0.f, 0.f);
    for (int i = 0; i < n; i++) {
        int2 p = ep[s + i];
        float v = __int_as_float(p.y);
        int c = p.x;
        float tv[18];
#pragma unroll
        for (int pl = 0; pl < 6; pl++) {
            float4 t4 = *(const float4*)(T0 + ((size_t)pl * NN0 + c) * 4);
            tv[pl * 3 + 0] = t4.x; tv[pl * 3 + 1] = t4.y; tv[pl * 3 + 2] = t4.z;
        }
        float h0 = b4.x, h1 = b4.y, h2 = b4.z, h3 = b4.w;
#pragma unroll
        for (int k = 0; k < 18; k++) {
            float t = tv[k];
            const float4 w4 = *(const float4*)(Ws + k * 128 + c0);
            h0 = fmaf(t, w4.x, h0); h1 = fmaf(t, w4.y, h1);
            h2 = fmaf(t, w4.z, h2); h3 = fmaf(t, w4.w, h3);
        }
        h0 = fmaxf(h0, 0.f); h1 = fmaxf(h1, 0.f);
        h2 = fmaxf(h2, 0.f); h3 = fmaxf(h3, 0.f);
        acc.x = fmaf(v, h0, acc.x); acc.y = fmaf(v, h1, acc.y);
        acc.z = fmaf(v, h2, acc.z); acc.w = fmaf(v, h3, acc.w);
    }
    *(float4*)(T1 + (size_t)warp * 768 + c0) = acc;
}

// ---------------- F=128 gather (warp per dst node, float4) --------------------
template <bool SUB>
__global__ void gather128_k(const int* __restrict__ rowptr, const int* __restrict__ cnt,
                            const int2* __restrict__ ep, int cbase,
                            const float* __restrict__ Tin, int in_stride, int in_off,
                            float* __restrict__ Tout,
                            float coef, int out_off, int prev_off, int nnodes) {
    int gw = (blockIdx.x * blockDim.x + threadIdx.x) >> 5;
    int lane = threadIdx.x & 31;
    if (gw >= nnodes) return;
    int s = rowptr[cbase + gw], n = cnt[cbase + gw];
    const float* ip = Tin + in_off + lane * 4;
    float ax = 0.f, ay = 0.f, az = 0.f, aw = 0.f;
#pragma unroll 4
    for (int i = 0; i < n; i++) {
        int2 p = ep[s + i];
        float w = __int_as_float(p.y);
        float4 xv = *(const float4*)(ip + (size_t)p.x * in_stride);
        ax = fmaf(w, xv.x, ax); ay = fmaf(w, xv.y, ay);
        az = fmaf(w, xv.z, az); aw = fmaf(w, xv.w, aw);
    }
    float4 o;
    if (SUB) {
        float4 pr = *(const float4*)(Tout + (size_t)gw * 768 + prev_off + lane * 4);
        o = make_float4(coef * ax - pr.x, coef * ay - pr.y,
                        coef * az - pr.z, coef * aw - pr.w);
    } else {
        o = make_float4(coef * ax, coef * ay, coef * az, coef * aw);
    }
    *(float4*)(Tout + (size_t)gw * 768 + out_off + lane * 4) = o;
}

// ---------------- F=128 gather, two half-warps per node (float2) --------------
// For small node counts (layer 2): doubles warp-level parallelism.
template <bool SUB>
__global__ void gather128h_k(const int* __restrict__ rowptr, const int* __restrict__ cnt,
                             const int2* __restrict__ ep, int cbase,
                             const float* __restrict__ Tin, int in_stride, int in_off,
                             float* __restrict__ Tout,
                             float coef, int out_off, int prev_off, int nnodes) {
    int gw = (blockIdx.x * blockDim.x + threadIdx.x) >> 5;
    int lane = threadIdx.x & 31;
    int node = gw >> 1, half = gw & 1;
    if (node >= nnodes) return;
    int s = rowptr[cbase + node], n = cnt[cbase + node];
    int f = half * 64 + lane * 2;
    const float* ip = Tin + in_off + f;
    float ax = 0.f, ay = 0.f;
#pragma unroll 4
    for (int i = 0; i < n; i++) {
        int2 p = ep[s + i];
        float w = __int_as_float(p.y);
        float2 xv = *(const float2*)(ip + (size_t)p.x * in_stride);
        ax = fmaf(w, xv.x, ax); ay = fmaf(w, xv.y, ay);
    }
    float2 o;
    if (SUB) {
        float2 pr = *(const float2*)(Tout + (size_t)node * 768 + prev_off + f);
        o = make_float2(coef * ax - pr.x, coef * ay - pr.y);
    } else {
        o = make_float2(coef * ax, coef * ay);
    }
    *(float2*)(Tout + (size_t)node * 768 + out_off + f) = o;
}

// ---------------- tf32 tensor-core GEMM --------------------------------------
template <bool RELU>
__global__ void __launch_bounds__(256) gemm_tf32_k(const float* __restrict__ A,
                                                   const float* __restrict__ B,
                                                   const float* __restrict__ bias,
                                                   float* __restrict__ C,
                                                   int M, int N, int K) {
    __shared__ float As[2][16][68];
    __shared__ float Bs[2][16][132];
    const int tid = threadIdx.x;
    const int warp = tid >> 5, lane = tid & 31;
    const int g = lane >> 2, tg = lane & 3;
    const int m0 = (warp >> 2) * 32, n0 = (warp & 3) * 32;
    const int brow = blockIdx.y * 64, bcol = blockIdx.x * 128;

    const int am = tid >> 2, akq = (tid & 3) << 2;
    const int bk = tid >> 5, bn4 = (tid & 31) << 2;

    float acc[2][4][4];
#pragma unroll
    for (int i = 0; i < 2; i++)
#pragma unroll
        for (int j = 0; j < 4; j++)
#pragma unroll
            for (int q = 0; q < 4; q++) acc[i][j][q] = 0.f;

    const int KT = K / 16;
    float4 pa, pb0, pb1;
    {
        int gr = brow + am;
        pa = (gr < M) ? *(const float4*)(A + (size_t)gr * K + akq)
                      : make_float4(0.f, 0.f, 0.f, 0.f);
        pb0 = *(const float4*)(B + (size_t)bk * N + bcol + bn4);
        pb1 = *(const float4*)(B + (size_t)(bk + 8) * N + bcol + bn4);
        As[0][akq + 0][am] = tf32r(pa.x); As[0][akq + 1][am] = tf32r(pa.y);
        As[0][akq + 2][am] = tf32r(pa.z); As[0][akq + 3][am] = tf32r(pa.w);
        *(float4*)&Bs[0][bk][bn4] =
            make_float4(tf32r(pb0.x), tf32r(pb0.y), tf32r(pb0.z), tf32r(pb0.w));
        *(float4*)&Bs[0][bk + 8][bn4] =
            make_float4(tf32r(pb1.x), tf32r(pb1.y), tf32r(pb1.z), tf32r(pb1.w));
    }
    __syncthreads();

    for (int t = 0; t < KT; t++) {
        const int st = t & 1;
        if (t + 1 < KT) {
            int kk = (t + 1) * 16;
            int gr = brow + am;
            pa = (gr < M) ? *(const float4*)(A + (size_t)gr * K + kk + akq)
                          : make_float4(0.f, 0.f, 0.f, 0.f);
            pb0 = *(const float4*)(B + (size_t)(kk + bk) * N + bcol + bn4);
            pb1 = *(const float4*)(B + (size_t)(kk + bk + 8) * N + bcol + bn4);
        }
#pragma unroll
        for (int ks = 0; ks < 16; ks += 8) {
            unsigned af[2][4], bf[4][2];
#pragma unroll
            for (int mt = 0; mt < 2; mt++) {
                int mr = m0 + mt * 16 + g;
                af[mt][0] = __float_as_uint(As[st][ks + tg][mr]);
                af[mt][1] = __float_as_uint(As[st][ks + tg][mr + 8]);
                af[mt][2] = __float_as_uint(As[st][ks + tg + 4][mr]);
                af[mt][3] = __float_as_uint(As[st][ks + tg + 4][mr + 8]);
            }
#pragma unroll
            for (int nt = 0; nt < 4; nt++) {
                int nc = n0 + nt * 8 + g;
                bf[nt][0] = __float_as_uint(Bs[st][ks + tg][nc]);
                bf[nt][1] = __float_as_uint(Bs[st][ks + tg + 4][nc]);
            }
#pragma unroll
            for (int mt = 0; mt < 2; mt++)
#pragma unroll
                for (int nt = 0; nt < 4; nt++)
                    mma_tf32(acc[mt][nt][0], acc[mt][nt][1], acc[mt][nt][2], acc[mt][nt][3],
                             af[mt][0], af[mt][1], af[mt][2], af[mt][3],
                             bf[nt][0], bf[nt][1]);
        }
        __syncthreads();
        if (t + 1 < KT) {
            const int ns = (t + 1) & 1;
            As[ns][akq + 0][am] = tf32r(pa.x); As[ns][akq + 1][am] = tf32r(pa.y);
            As[ns][akq + 2][am] = tf32r(pa.z); As[ns][akq + 3][am] = tf32r(pa.w);
            *(float4*)&Bs[ns][bk][bn4] =
                make_float4(tf32r(pb0.x), tf32r(pb0.y), tf32r(pb0.z), tf32r(pb0.w));
            *(float4*)&Bs[ns][bk + 8][bn4] =
                make_float4(tf32r(pb1.x), tf32r(pb1.y), tf32r(pb1.z), tf32r(pb1.w));
            __syncthreads();
        }
    }

#pragma unroll
    for (int mt = 0; mt < 2; mt++) {
        int r0 = brow + m0 + mt * 16 + g;
        int r1 = r0 + 8;
#pragma unroll
        for (int nt = 0; nt < 4; nt++) {
            int cb = bcol + n0 + nt * 8 + 2 * tg;
            float bx = bias[cb], by = bias[cb + 1];
            float v0 = acc[mt][nt][0] + bx, v1 = acc[mt][nt][1] + by;
            float v2 = acc[mt][nt][2] + bx, v3 = acc[mt][nt][3] + by;
            if (RELU) {
                v0 = fmaxf(v0, 0.f); v1 = fmaxf(v1, 0.f);
                v2 = fmaxf(v2, 0.f); v3 = fmaxf(v3, 0.f);
            }
            if (r0 < M) *(float2*)(C + (size_t)r0 * N + cb) = make_float2(v0, v1);
            if (r1 < M) *(float2*)(C + (size_t)r1 * N + cb) = make_float2(v2, v3);
        }
    }
}

// ---------------- final linear (out pre-initialized with linb) ---------------
__global__ void __launch_bounds__(256) final_k(const float* __restrict__ h,
                                               const float* __restrict__ W,
                                               float* __restrict__ out) {
    const int NT = NN2 * 256;
    const int NT4 = NT / 4;
    float acc[10];
#pragma unroll
    for (int r = 0; r < 10; r++) acc[r] = 0.f;
    int stride = gridDim.x * blockDim.x;
    const float4* h4 = (const float4*)h;
    for (int idx = blockIdx.x * blockDim.x + threadIdx.x; idx < NT4; idx += stride) {
        float4 hv = h4[idx];
#pragma unroll
        for (int r = 0; r < 10; r++) {
            float4 wv = *(const float4*)(W + (size_t)r * NT + idx * 4);
            acc[r] += hv.x * wv.x + hv.y * wv.y + hv.z * wv.z + hv.w * wv.w;
        }
    }
#pragma unroll
    for (int off = 16; off; off >>= 1)
#pragma unroll
        for (int r = 0; r < 10; r++) acc[r] += __shfl_down_sync(0xffffffffu, acc[r], off);
    __shared__ float part[8][10];
    int warp = threadIdx.x >> 5, lane = threadIdx.x & 31;
    if (lane == 0)
        for (int r = 0; r < 10; r++) part[warp][r] = acc[r];
    __syncthreads();
    if (threadIdx.x < 10) {
        float s = 0.f;
#pragma unroll
        for (int wv = 0; wv < 8; wv++) s += part[wv][threadIdx.x];
        atomicAdd(&out[threadIdx.x], s);
    }
}

// ---------------- host orchestration ----------------------------------------
extern "C" void kernel_launch(void* const* d_in, const int* in_sizes, int n_in,
                              void* d_out, int out_size) {
    const float* x    = (const float*)d_in[0];
    const int*   ei0  = (const int*)d_in[1];
    const int*   ei1  = (const int*)d_in[2];
    const int*   ei2  = (const int*)d_in[3];
    const float* W0   = (const float*)d_in[4];
    const float* b0   = (const float*)d_in[5];
    const float* W1   = (const float*)d_in[6];
    const float* b1   = (const float*)d_in[7];
    const float* W2   = (const float*)d_in[8];
    const float* b2   = (const float*)d_in[9];
    const int*   D0r  = (const int*)d_in[10];
    const int*   D0c  = (const int*)d_in[11];
    const float* D0v  = (const float*)d_in[12];
    const int*   D1r  = (const int*)d_in[13];
    const int*   D1c  = (const int*)d_in[14];
    const float* D1v  = (const float*)d_in[15];
    const float* linW = (const float*)d_in[16];
    const float* linb = (const float*)d_in[17];
    float* out = (float*)d_out;

    float *dinv0, *dinv1, *dinv2, *T0, *T1, *h1, *T2, *h2;
    int *cnt, *rowptr, *fill, *bsum;
    unsigned* bars;
    int2* ep;
    cudaGetSymbolAddress((void**)&dinv0, g_dinv0);
    cudaGetSymbolAddress((void**)&dinv1, g_dinv1);
    cudaGetSymbolAddress((void**)&dinv2, g_dinv2);
    cudaGetSymbolAddress((void**)&cnt, g_cnt);
    cudaGetSymbolAddress((void**)&rowptr, g_rowptr);
    cudaGetSymbolAddress((void**)&fill, g_fill);
    cudaGetSymbolAddress((void**)&bsum, g_bsum);
    cudaGetSymbolAddress((void**)&bars, g_bars);
    cudaGetSymbolAddress((void**)&ep, g_epack);
    cudaGetSymbolAddress((void**)&T0, g_T0);
    cudaGetSymbolAddress((void**)&T1, g_T1);
    cudaGetSymbolAddress((void**)&h1, g_h1);
    cudaGetSymbolAddress((void**)&T2, g_T2);
    cudaGetSymbolAddress((void**)&h2, g_h2);

    const int TB = 256;

    // ---- zeroing via memset nodes (not kernel launches) ----
    cudaMemsetAsync(cnt, 0, sizeof(int) * CNT_TOT);
    cudaMemsetAsync(dinv0, 0, sizeof(float) * NN0);
    cudaMemsetAsync(dinv1, 0, sizeof(float) * NN1);
    cudaMemsetAsync(dinv2, 0, sizeof(float) * NN2);
    cudaMemsetAsync(bars, 0, sizeof(unsigned) * 4);

    // ---- CSR build (3 graphs + 2 pool matrices, concatenated) ----
    hist_k<<<cdiv(ETOT_ALL, TB), TB>>>(ei0, ei1, ei2, D0r, D1r,
                                       dinv0, dinv1, dinv2, cnt);
    scanfused_k<<<NSCAN_BLKS, SCAN_BLK>>>(cnt, rowptr, fill, bsum,
                                          dinv0, dinv1, dinv2, linb, out, &bars[0]);
    fill_k<<<cdiv(ETOT_ALL, TB), TB>>>(ei0, ei1, ei2, D0r, D0c, D0v,
                                       D1r, D1c, D1v, dinv0, dinv1, dinv2,
                                       fill, ep, x, T0);

    // ---- layer 0: 5 Chebyshev propagations, 4 threads/node ----
    {
        int g0 = cdiv(NN0 * 4, TB);
        gather3q_k<false><<<g0, TB>>>(rowptr, cnt, ep, T0, 1.f, 0, 1, 0);
        gather3q_k<true><<<g0, TB>>>(rowptr, cnt, ep, T0, 2.f, 1, 2, 0);
        gather3q_k<true><<<g0, TB>>>(rowptr, cnt, ep, T0, 2.f, 2, 3, 1);
        gather3q_k<true><<<g0, TB>>>(rowptr, cnt, ep, T0, 2.f, 3, 4, 2);
        gather3q_k<true><<<g0, TB>>>(rowptr, cnt, ep, T0, 2.f, 4, 5, 3);
    }

    // ---- fused gemm0 + pool0 -> T1 col0 ----
    poolgemm0_k<<<cdiv(NN1 * 32, TB), TB>>>(rowptr, cnt, ep, T0, W0, b0, T1);

    // ---- layer 1 (warp per node; 25k warps saturates chip) ----
    gather128_k<false><<<cdiv(NN1 * 32, TB), TB>>>(rowptr, cnt, ep, CB1, T1, 768, 0,
                                                   T1, 1.f, 128, 0, NN1);
    gather128_k<true><<<cdiv(NN1 * 32, TB), TB>>>(rowptr, cnt, ep, CB1, T1, 768, 128,
                                                  T1, 2.f, 256, 0, NN1);
    gather128_k<true><<<cdiv(NN1 * 32, TB), TB>>>(rowptr, cnt, ep, CB1, T1, 768, 256,
                                                  T1, 2.f, 384, 128, NN1);
    gather128_k<true><<<cdiv(NN1 * 32, TB), TB>>>(rowptr, cnt, ep, CB1, T1, 768, 384,
                                                  T1, 2.f, 512, 256, NN1);
    gather128_k<true><<<cdiv(NN1 * 32, TB), TB>>>(rowptr, cnt, ep, CB1, T1, 768, 512,
                                                  T1, 2.f, 640, 384, NN1);
    {
        dim3 grid(1, cdiv(NN1, 64));
        gemm_tf32_k<true><<<grid, 256>>>(T1, W1, b1, h1, NN1, 128, 768);
    }

    // ---- pool 1 -> T2 col0 + layer 2 (two half-warps per node) ----
    {
        int g2 = cdiv(NN2 * 2 * 32, TB);
        gather128h_k<false><<<g2, TB>>>(rowptr, cnt, ep, CBD1, h1, 128, 0,
                                        T2, 1.f, 0, 0, NN2);
        gather128h_k<false><<<g2, TB>>>(rowptr, cnt, ep, CB2, T2, 768, 0,
                                        T2, 1.f, 128, 0, NN2);
        gather128h_k<true><<<g2, TB>>>(rowptr, cnt, ep, CB2, T2, 768, 128,
                                       T2, 2.f, 256, 0, NN2);
        gather128h_k<true><<<g2, TB>>>(rowptr, cnt, ep, CB2, T2, 768, 256,
                                       T2, 2.f, 384, 128, NN2);
        gather128h_k<true><<<g2, TB>>>(rowptr, cnt, ep, CB2, T2, 768, 384,
                                       T2, 2.f, 512, 256, NN2);
        gather128h_k<true><<<g2, TB>>>(rowptr, cnt, ep, CB2, T2, 768, 512,
                                       T2, 2.f, 640, 384, NN2);
    }
    {
        dim3 grid(2, cdiv(NN2, 64));
        gemm_tf32_k<false><<<grid, 256>>>(T2, W2, b2, h2, NN2, 256, 768);
    }

    // ---- final linear ----
    final_k<<<1184, 256>>>(h2, linW, out);
}

// round 12
// speedup vs baseline: 1.0238x; 1.0238x over previous
#include <cuda_runtime.h>

#define NN0 100000
#define NN1 25000
#define NN2 6250
#define EE0 600000
#define EE1 150000
#define EE2 37500
#define ED0 100000
#define ED1 25000

// concatenated count bases: [g0][g1][g2][D0 rows][D1 rows]
#define CB0 0
#define CB1 NN0
#define CB2 (NN0 + NN1)
#define CBD0 (NN0 + NN1 + NN2)
#define CBD1 (CBD0 + NN1)
#define CNT_TOT (CBD1 + NN2)                 // 162500
#define ETOT_ALL (EE0 + EE1 + EE2 + ED0 + ED1)  // 912500
#define SCAN_BLK 1024
#define NSCAN_BLKS ((CNT_TOT + SCAN_BLK - 1) / SCAN_BLK)  // 159

// ---------------- scratch (device globals; no allocations allowed) ----------
__device__ __align__(16) float g_dinv0[NN0], g_dinv1[NN1], g_dinv2[NN2];
__device__ __align__(16) int g_cnt[CNT_TOT];
__device__ __align__(16) int g_rowptr[CNT_TOT];
__device__ __align__(16) int g_fill[CNT_TOT];
__device__ __align__(16) int g_bsum[NSCAN_BLKS];
__device__ __align__(16) unsigned g_bars[4];
__device__ __align__(16) int2 g_epack[ETOT_ALL];   // (src, w bits)
__device__ __align__(16) float g_T0[(size_t)NN0 * 24];   // 6 planes of [NN0,4]
__device__ __align__(16) float g_T1[(size_t)NN1 * 768];
__device__ __align__(16) float g_h1[(size_t)NN1 * 128];
__device__ __align__(16) float g_T2[(size_t)NN2 * 768];
__device__ __align__(16) float g_h2[(size_t)NN2 * 256];

static inline int cdiv(int a, int b) { return (a + b - 1) / b; }

// ---------------- helpers ----------------------------------------------------
__device__ __forceinline__ float tf32r(float x) {
    unsigned u;
    asm("cvt.rna.tf32.f32 %0, %1;" : "=r"(u) : "f"(x));
    return __uint_as_float(u);
}

__device__ __forceinline__ void mma_tf32(float& c0, float& c1, float& c2, float& c3,
                                         unsigned a0, unsigned a1, unsigned a2, unsigned a3,
                                         unsigned b0, unsigned b1) {
    asm volatile(
        "mma.sync.aligned.m16n8k8.row.col.f32.tf32.tf32.f32 "
        "{%0,%1,%2,%3},{%4,%5,%6,%7},{%8,%9},{%0,%1,%2,%3};"
        : "+f"(c0), "+f"(c1), "+f"(c2), "+f"(c3)
        : "r"(a0), "r"(a1), "r"(a2), "r"(a3), "r"(b0), "r"(b1));
}

__device__ __forceinline__ void gbar(unsigned* bar, unsigned target) {
    __threadfence();
    __syncthreads();
    if (threadIdx.x == 0) {
        atomicAdd(bar, 1u);
        while (*((volatile unsigned*)bar) < target) {}
        __threadfence();
    }
    __syncthreads();
}

// ---------------- CSR build ---------------------------------------------------
__global__ void hist_k(const int* e0, const int* e1, const int* e2,
                       const int* d0r, const int* d1r,
                       float* dv0, float* dv1, float* dv2, int* __restrict__ cnt) {
    int i = blockIdx.x * blockDim.x + threadIdx.x;
    if (i < EE0) {
        atomicAdd(&dv0[e0[i]], 1.f);
        atomicAdd(&cnt[CB0 + e0[EE0 + i]], 1);
        return;
    }
    i -= EE0;
    if (i < EE1) {
        atomicAdd(&dv1[e1[i]], 1.f);
        atomicAdd(&cnt[CB1 + e1[EE1 + i]], 1);
        return;
    }
    i -= EE1;
    if (i < EE2) {
        atomicAdd(&dv2[e2[i]], 1.f);
        atomicAdd(&cnt[CB2 + e2[EE2 + i]], 1);
        return;
    }
    i -= EE2;
    if (i < ED0) { atomicAdd(&cnt[CBD0 + d0r[i]], 1); return; }
    i -= ED0;
    if (i < ED1) atomicAdd(&cnt[CBD1 + d1r[i]], 1);
}

// fused: dinv + per-block scan + cross-block prefix + rowptr/fill + out init
__global__ __launch_bounds__(1024, 2) void scanfused_k(
    const int* __restrict__ cnt, int* __restrict__ rowptr, int* __restrict__ fill,
    int* __restrict__ bsum, float* d0, float* d1, float* d2,
    const float* __restrict__ linb, float* __restrict__ out, unsigned* bar) {
    __shared__ int sm[SCAN_BLK];
    __shared__ int bsm[NSCAN_BLKS];
    __shared__ int boff_sh;
    int t = threadIdx.x;
    int gid = blockIdx.x * SCAN_BLK + t;

    if (gid < 10) out[gid] = linb[gid];

    if (gid < NN0) { float v = d0[gid]; d0[gid] = v > 0.f ? rsqrtf(v) : 0.f; }
    else {
        int j = gid - NN0;
        if (j < NN1) { float v = d1[j]; d1[j] = v > 0.f ? rsqrtf(v) : 0.f; }
        else {
            int k = j - NN1;
            if (k < NN2) { float v = d2[k]; d2[k] = v > 0.f ? rsqrtf(v) : 0.f; }
        }
    }

    int v = (gid < CNT_TOT) ? cnt[gid] : 0;
    sm[t] = v;
    __syncthreads();
    for (int off = 1; off < SCAN_BLK; off <<= 1) {
        int add = (t >= off) ? sm[t - off] : 0;
        __syncthreads();
        sm[t] += add;
        __syncthreads();
    }
    if (t == SCAN_BLK - 1) bsum[blockIdx.x] = sm[t];

    gbar(bar, gridDim.x);

    if (t < NSCAN_BLKS) bsm[t] = bsum[t];
    __syncthreads();
    if (t == 0) {
        int a = 0;
        for (int i = 0; i < (int)blockIdx.x; i++) a += bsm[i];
        boff_sh = a;
    }
    __syncthreads();
    if (gid < CNT_TOT) {
        int start = sm[t] - v + boff_sh;
        rowptr[gid] = start;
        fill[gid] = start;
    }
}

// fill CSR edge arrays (src, weight) grouped by dst; also init T0 plane 0
__global__ void fill_k(const int* e0, const int* e1, const int* e2,
                       const int* d0r, const int* d0c, const float* d0v,
                       const int* d1r, const int* d1c, const float* d1v,
                       const float* dv0, const float* dv1, const float* dv2,
                       int* __restrict__ fill, int2* __restrict__ ep,
                       const float* __restrict__ x, float* __restrict__ T0) {
    int i = blockIdx.x * blockDim.x + threadIdx.x;
    if (i < NN0)
        *(float4*)(T0 + (size_t)i * 4) =
            make_float4(x[3 * i], x[3 * i + 1], x[3 * i + 2], 0.f);
    int src, cb; float w;
    if (i < EE0) {
        src = e0[i]; int dst = e0[EE0 + i];
        w = -dv0[src] * dv0[dst]; cb = CB0 + dst;
    } else if ((i -= EE0) < EE1) {
        src = e1[i]; int dst = e1[EE1 + i];
        w = -dv1[src] * dv1[dst]; cb = CB1 + dst;
    } else if ((i -= EE1) < EE2) {
        src = e2[i]; int dst = e2[EE2 + i];
        w = -dv2[src] * dv2[dst]; cb = CB2 + dst;
    } else if ((i -= EE2) < ED0) {
        src = d0c[i]; w = d0v[i]; cb = CBD0 + d0r[i];
    } else if ((i -= ED0) < ED1) {
        src = d1c[i]; w = d1v[i]; cb = CBD1 + d1r[i];
    } else return;
    int pos = atomicAdd(&fill[cb], 1);
    ep[pos] = make_int2(src, __float_as_int(w));
}

// ---------------- layer-0 propagation (thread per dst node) ------------------
template <bool SUB>
__global__ void gather3_k(const int* __restrict__ rowptr, const int* __restrict__ cnt,
                          const int2* __restrict__ ep, float* __restrict__ T,
                          float coef, int in_p, int out_p, int prev_p) {
    int node = blockIdx.x * blockDim.x + threadIdx.x;
    if (node >= NN0) return;
    int s = rowptr[node], n = cnt[node];
    const float* Tin = T + (size_t)in_p * NN0 * 4;
    float ax = 0.f, ay = 0.f, az = 0.f;
#pragma unroll 4
    for (int i = 0; i < n; i++) {
        int2 p = ep[s + i];
        float w = __int_as_float(p.y);
        float4 xv = *(const float4*)(Tin + (size_t)p.x * 4);
        ax = fmaf(w, xv.x, ax); ay = fmaf(w, xv.y, ay); az = fmaf(w, xv.z, az);
    }
    float4 o;
    if (SUB) {
        float4 pr = *(const float4*)(T + ((size_t)prev_p * NN0 + node) * 4);
        o = make_float4(coef * ax - pr.x, coef * ay - pr.y, coef * az - pr.z, 0.f);
    } else {
        o = make_float4(coef * ax, coef * ay, coef * az, 0.f);
    }
    *(float4*)(T + ((size_t)out_p * NN0 + node) * 4) = o;
}

// ---------------- fused gemm0(+relu) + pool0, W in registers -----------------
// warp per pooled row; each lane owns output cols c0..c0+3 and caches its
// 18x4 slice of W0 in registers (no smem in the inner loop -> FMA-bound).
__global__ void __launch_bounds__(256) poolgemm0_k(const int* __restrict__ rowptr,
                                                   const int* __restrict__ cnt,
                                                   const int2* __restrict__ ep,
                                                   const float* __restrict__ T0,
                                                   const float* __restrict__ W,
                                                   const float* __restrict__ bias,
                                                   float* __restrict__ T1) {
    int tid = threadIdx.x;
    int lane = tid & 31;
    int warp = (blockIdx.x * 256 + tid) >> 5;
    int c0 = lane * 4;
    // register-cached weight slice: Wr[k] = W[k][c0..c0+3]
    float4 Wr[18];
#pragma unroll
    for (int k = 0; k < 18; k++) Wr[k] = *(const float4*)(W + k * 128 + c0);
    if (warp >= NN1) return;
    float4 b4 = *(const float4*)(bias + c0);
    int s = rowptr[CBD0 + warp], n = cnt[CBD0 + warp];
    float4 acc = make_float4(0.f, 0.f, 0.f, 0.f);
    for (int i = 0; i < n; i++) {
        int2 p = ep[s + i];
        float v = __int_as_float(p.y);
        int c = p.x;
        float h0 = b4.x, h1 = b4.y, h2 = b4.z, h3 = b4.w;
#pragma unroll
        for (int pl = 0; pl < 6; pl++) {
            float4 t4 = *(const float4*)(T0 + ((size_t)pl * NN0 + c) * 4);
            const float4 w0 = Wr[pl * 3 + 0];
            const float4 w1 = Wr[pl * 3 + 1];
            const float4 w2 = Wr[pl * 3 + 2];
            h0 = fmaf(t4.x, w0.x, h0); h1 = fmaf(t4.x, w0.y, h1);
            h2 = fmaf(t4.x, w0.z, h2); h3 = fmaf(t4.x, w0.w, h3);
            h0 = fmaf(t4.y, w1.x, h0); h1 = fmaf(t4.y, w1.y, h1);
            h2 = fmaf(t4.y, w1.z, h2); h3 = fmaf(t4.y, w1.w, h3);
            h0 = fmaf(t4.z, w2.x, h0); h1 = fmaf(t4.z, w2.y, h1);
            h2 = fmaf(t4.z, w2.z, h2); h3 = fmaf(t4.z, w2.w, h3);
        }
        h0 = fmaxf(h0, 0.f); h1 = fmaxf(h1, 0.f);
        h2 = fmaxf(h2, 0.f); h3 = fmaxf(h3, 0.f);
        acc.x = fmaf(v, h0, acc.x); acc.y = fmaf(v, h1, acc.y);
        acc.z = fmaf(v, h2, acc.z); acc.w = fmaf(v, h3, acc.w);
    }
    *(float4*)(T1 + (size_t)warp * 768 + c0) = acc;
}

// ---------------- F=128 gather (warp per dst node, float4) --------------------
template <bool SUB>
__global__ void gather128_k(const int* __restrict__ rowptr, const int* __restrict__ cnt,
                            const int2* __restrict__ ep, int cbase,
                            const float* __restrict__ Tin, int in_stride, int in_off,
                            float* __restrict__ Tout,
                            float coef, int out_off, int prev_off, int nnodes) {
    int gw = (blockIdx.x * blockDim.x + threadIdx.x) >> 5;
    int lane = threadIdx.x & 31;
    if (gw >= nnodes) return;
    int s = rowptr[cbase + gw], n = cnt[cbase + gw];
    const float* ip = Tin + in_off + lane * 4;
    float ax = 0.f, ay = 0.f, az = 0.f, aw = 0.f;
#pragma unroll 4
    for (int i = 0; i < n; i++) {
        int2 p = ep[s + i];
        float w = __int_as_float(p.y);
        float4 xv = *(const float4*)(ip + (size_t)p.x * in_stride);
        ax = fmaf(w, xv.x, ax); ay = fmaf(w, xv.y, ay);
        az = fmaf(w, xv.z, az); aw = fmaf(w, xv.w, aw);
    }
    float4 o;
    if (SUB) {
        float4 pr = *(const float4*)(Tout + (size_t)gw * 768 + prev_off + lane * 4);
        o = make_float4(coef * ax - pr.x, coef * ay - pr.y,
                        coef * az - pr.z, coef * aw - pr.w);
    } else {
        o = make_float4(coef * ax, coef * ay, coef * az, coef * aw);
    }
    *(float4*)(Tout + (size_t)gw * 768 + out_off + lane * 4) = o;
}

// ---------------- F=128 gather, two half-warps per node (float2) --------------
template <bool SUB>
__global__ void gather128h_k(const int* __restrict__ rowptr, const int* __restrict__ cnt,
                             const int2* __restrict__ ep, int cbase,
                             const float* __restrict__ Tin, int in_stride, int in_off,
                             float* __restrict__ Tout,
                             float coef, int out_off, int prev_off, int nnodes) {
    int gw = (blockIdx.x * blockDim.x + threadIdx.x) >> 5;
    int lane = threadIdx.x & 31;
    int node = gw >> 1, half = gw & 1;
    if (node >= nnodes) return;
    int s = rowptr[cbase + node], n = cnt[cbase + node];
    int f = half * 64 + lane * 2;
    const float* ip = Tin + in_off + f;
    float ax = 0.f, ay = 0.f;
#pragma unroll 4
    for (int i = 0; i < n; i++) {
        int2 p = ep[s + i];
        float w = __int_as_float(p.y);
        float2 xv = *(const float2*)(ip + (size_t)p.x * in_stride);
        ax = fmaf(w, xv.x, ax); ay = fmaf(w, xv.y, ay);
    }
    float2 o;
    if (SUB) {
        float2 pr = *(const float2*)(Tout + (size_t)node * 768 + prev_off + f);
        o = make_float2(coef * ax - pr.x, coef * ay - pr.y);
    } else {
        o = make_float2(coef * ax, coef * ay);
    }
    *(float2*)(Tout + (size_t)node * 768 + out_off + f) = o;
}

// ---------------- tf32 tensor-core GEMM --------------------------------------
template <bool RELU>
__global__ void __launch_bounds__(256) gemm_tf32_k(const float* __restrict__ A,
                                                   const float* __restrict__ B,
                                                   const float* __restrict__ bias,
                                                   float* __restrict__ C,
                                                   int M, int N, int K) {
    __shared__ float As[2][16][68];
    __shared__ float Bs[2][16][132];
    const int tid = threadIdx.x;
    const int warp = tid >> 5, lane = tid & 31;
    const int g = lane >> 2, tg = lane & 3;
    const int m0 = (warp >> 2) * 32, n0 = (warp & 3) * 32;
    const int brow = blockIdx.y * 64, bcol = blockIdx.x * 128;

    const int am = tid >> 2, akq = (tid & 3) << 2;
    const int bk = tid >> 5, bn4 = (tid & 31) << 2;

    float acc[2][4][4];
#pragma unroll
    for (int i = 0; i < 2; i++)
#pragma unroll
        for (int j = 0; j < 4; j++)
#pragma unroll
            for (int q = 0; q < 4; q++) acc[i][j][q] = 0.f;

    const int KT = K / 16;
    float4 pa, pb0, pb1;
    {
        int gr = brow + am;
        pa = (gr < M) ? *(const float4*)(A + (size_t)gr * K + akq)
                      : make_float4(0.f, 0.f, 0.f, 0.f);
        pb0 = *(const float4*)(B + (size_t)bk * N + bcol + bn4);
        pb1 = *(const float4*)(B + (size_t)(bk + 8) * N + bcol + bn4);
        As[0][akq + 0][am] = tf32r(pa.x); As[0][akq + 1][am] = tf32r(pa.y);
        As[0][akq + 2][am] = tf32r(pa.z); As[0][akq + 3][am] = tf32r(pa.w);
        *(float4*)&Bs[0][bk][bn4] =
            make_float4(tf32r(pb0.x), tf32r(pb0.y), tf32r(pb0.z), tf32r(pb0.w));
        *(float4*)&Bs[0][bk + 8][bn4] =
            make_float4(tf32r(pb1.x), tf32r(pb1.y), tf32r(pb1.z), tf32r(pb1.w));
    }
    __syncthreads();

    for (int t = 0; t < KT; t++) {
        const int st = t & 1;
        if (t + 1 < KT) {
            int kk = (t + 1) * 16;
            int gr = brow + am;
            pa = (gr < M) ? *(const float4*)(A + (size_t)gr * K + kk + akq)
                          : make_float4(0.f, 0.f, 0.f, 0.f);
            pb0 = *(const float4*)(B + (size_t)(kk + bk) * N + bcol + bn4);
            pb1 = *(const float4*)(B + (size_t)(kk + bk + 8) * N + bcol + bn4);
        }
#pragma unroll
        for (int ks = 0; ks < 16; ks += 8) {
            unsigned af[2][4], bf[4][2];
#pragma unroll
            for (int mt = 0; mt < 2; mt++) {
                int mr = m0 + mt * 16 + g;
                af[mt][0] = __float_as_uint(As[st][ks + tg][mr]);
                af[mt][1] = __float_as_uint(As[st][ks + tg][mr + 8]);
                af[mt][2] = __float_as_uint(As[st][ks + tg + 4][mr]);
                af[mt][3] = __float_as_uint(As[st][ks + tg + 4][mr + 8]);
            }
#pragma unroll
            for (int nt = 0; nt < 4; nt++) {
                int nc = n0 + nt * 8 + g;
                bf[nt][0] = __float_as_uint(Bs[st][ks + tg][nc]);
                bf[nt][1] = __float_as_uint(Bs[st][ks + tg + 4][nc]);
            }
#pragma unroll
            for (int mt = 0; mt < 2; mt++)
#pragma unroll
                for (int nt = 0; nt < 4; nt++)
                    mma_tf32(acc[mt][nt][0], acc[mt][nt][1], acc[mt][nt][2], acc[mt][nt][3],
                             af[mt][0], af[mt][1], af[mt][2], af[mt][3],
                             bf[nt][0], bf[nt][1]);
        }
        __syncthreads();
        if (t + 1 < KT) {
            const int ns = (t + 1) & 1;
            As[ns][akq + 0][am] = tf32r(pa.x); As[ns][akq + 1][am] = tf32r(pa.y);
            As[ns][akq + 2][am] = tf32r(pa.z); As[ns][akq + 3][am] = tf32r(pa.w);
            *(float4*)&Bs[ns][bk][bn4] =
                make_float4(tf32r(pb0.x), tf32r(pb0.y), tf32r(pb0.z), tf32r(pb0.w));
            *(float4*)&Bs[ns][bk + 8][bn4] =
                make_float4(tf32r(pb1.x), tf32r(pb1.y), tf32r(pb1.z), tf32r(pb1.w));
            __syncthreads();
        }
    }

#pragma unroll
    for (int mt = 0; mt < 2; mt++) {
        int r0 = brow + m0 + mt * 16 + g;
        int r1 = r0 + 8;
#pragma unroll
        for (int nt = 0; nt < 4; nt++) {
            int cb = bcol + n0 + nt * 8 + 2 * tg;
            float bx = bias[cb], by = bias[cb + 1];
            float v0 = acc[mt][nt][0] + bx, v1 = acc[mt][nt][1] + by;
            float v2 = acc[mt][nt][2] + bx, v3 = acc[mt][nt][3] + by;
            if (RELU) {
                v0 = fmaxf(v0, 0.f); v1 = fmaxf(v1, 0.f);
                v2 = fmaxf(v2, 0.f); v3 = fmaxf(v3, 0.f);
            }
            if (r0 < M) *(float2*)(C + (size_t)r0 * N + cb) = make_float2(v0, v1);
            if (r1 < M) *(float2*)(C + (size_t)r1 * N + cb) = make_float2(v2, v3);
        }
    }
}

// ---------------- final linear (out pre-initialized with linb) ---------------
__global__ void __launch_bounds__(256) final_k(const float* __restrict__ h,
                                               const float* __restrict__ W,
                                               float* __restrict__ out) {
    const int NT = NN2 * 256;
    const int NT4 = NT / 4;
    float acc[10];
#pragma unroll
    for (int r = 0; r < 10; r++) acc[r] = 0.f;
    int stride = gridDim.x * blockDim.x;
    const float4* h4 = (const float4*)h;
    for (int idx = blockIdx.x * blockDim.x + threadIdx.x; idx < NT4; idx += stride) {
        float4 hv = h4[idx];
#pragma unroll
        for (int r = 0; r < 10; r++) {
            float4 wv = *(const float4*)(W + (size_t)r * NT + idx * 4);
            acc[r] += hv.x * wv.x + hv.y * wv.y + hv.z * wv.z + hv.w * wv.w;
        }
    }
#pragma unroll
    for (int off = 16; off; off >>= 1)
#pragma unroll
        for (int r = 0; r < 10; r++) acc[r] += __shfl_down_sync(0xffffffffu, acc[r], off);
    __shared__ float part[8][10];
    int warp = threadIdx.x >> 5, lane = threadIdx.x & 31;
    if (lane == 0)
        for (int r = 0; r < 10; r++) part[warp][r] = acc[r];
    __syncthreads();
    if (threadIdx.x < 10) {
        float s = 0.f;
#pragma unroll
        for (int wv = 0; wv < 8; wv++) s += part[wv][threadIdx.x];
        atomicAdd(&out[threadIdx.x], s);
    }
}

// ---------------- host orchestration ----------------------------------------
extern "C" void kernel_launch(void* const* d_in, const int* in_sizes, int n_in,
                              void* d_out, int out_size) {
    const float* x    = (const float*)d_in[0];
    const int*   ei0  = (const int*)d_in[1];
    const int*   ei1  = (const int*)d_in[2];
    const int*   ei2  = (const int*)d_in[3];
    const float* W0   = (const float*)d_in[4];
    const float* b0   = (const float*)d_in[5];
    const float* W1   = (const float*)d_in[6];
    const float* b1   = (const float*)d_in[7];
    const float* W2   = (const float*)d_in[8];
    const float* b2   = (const float*)d_in[9];
    const int*   D0r  = (const int*)d_in[10];
    const int*   D0c  = (const int*)d_in[11];
    const float* D0v  = (const float*)d_in[12];
    const int*   D1r  = (const int*)d_in[13];
    const int*   D1c  = (const int*)d_in[14];
    const float* D1v  = (const float*)d_in[15];
    const float* linW = (const float*)d_in[16];
    const float* linb = (const float*)d_in[17];
    float* out = (float*)d_out;

    float *dinv0, *dinv1, *dinv2, *T0, *T1, *h1, *T2, *h2;
    int *cnt, *rowptr, *fill, *bsum;
    unsigned* bars;
    int2* ep;
    cudaGetSymbolAddress((void**)&dinv0, g_dinv0);
    cudaGetSymbolAddress((void**)&dinv1, g_dinv1);
    cudaGetSymbolAddress((void**)&dinv2, g_dinv2);
    cudaGetSymbolAddress((void**)&cnt, g_cnt);
    cudaGetSymbolAddress((void**)&rowptr, g_rowptr);
    cudaGetSymbolAddress((void**)&fill, g_fill);
    cudaGetSymbolAddress((void**)&bsum, g_bsum);
    cudaGetSymbolAddress((void**)&bars, g_bars);
    cudaGetSymbolAddress((void**)&ep, g_epack);
    cudaGetSymbolAddress((void**)&T0, g_T0);
    cudaGetSymbolAddress((void**)&T1, g_T1);
    cudaGetSymbolAddress((void**)&h1, g_h1);
    cudaGetSymbolAddress((void**)&T2, g_T2);
    cudaGetSymbolAddress((void**)&h2, g_h2);

    const int TB = 256;

    // ---- zeroing via memset nodes (not kernel launches) ----
    cudaMemsetAsync(cnt, 0, sizeof(int) * CNT_TOT);
    cudaMemsetAsync(dinv0, 0, sizeof(float) * NN0);
    cudaMemsetAsync(dinv1, 0, sizeof(float) * NN1);
    cudaMemsetAsync(dinv2, 0, sizeof(float) * NN2);
    cudaMemsetAsync(bars, 0, sizeof(unsigned) * 4);

    // ---- CSR build (3 graphs + 2 pool matrices, concatenated) ----
    hist_k<<<cdiv(ETOT_ALL, TB), TB>>>(ei0, ei1, ei2, D0r, D1r,
                                       dinv0, dinv1, dinv2, cnt);
    scanfused_k<<<NSCAN_BLKS, SCAN_BLK>>>(cnt, rowptr, fill, bsum,
                                          dinv0, dinv1, dinv2, linb, out, &bars[0]);
    fill_k<<<cdiv(ETOT_ALL, TB), TB>>>(ei0, ei1, ei2, D0r, D0c, D0v,
                                       D1r, D1c, D1v, dinv0, dinv1, dinv2,
                                       fill, ep, x, T0);

    // ---- layer 0: 5 Chebyshev propagations, thread per node ----
    {
        int g0 = cdiv(NN0, TB);
        gather3_k<false><<<g0, TB>>>(rowptr, cnt, ep, T0, 1.f, 0, 1, 0);
        gather3_k<true><<<g0, TB>>>(rowptr, cnt, ep, T0, 2.f, 1, 2, 0);
        gather3_k<true><<<g0, TB>>>(rowptr, cnt, ep, T0, 2.f, 2, 3, 1);
        gather3_k<true><<<g0, TB>>>(rowptr, cnt, ep, T0, 2.f, 3, 4, 2);
        gather3_k<true><<<g0, TB>>>(rowptr, cnt, ep, T0, 2.f, 4, 5, 3);
    }

    // ---- fused gemm0 + pool0 -> T1 col0 (W0 register-cached) ----
    poolgemm0_k<<<cdiv(NN1 * 32, TB), TB>>>(rowptr, cnt, ep, T0, W0, b0, T1);

    // ---- layer 1 (warp per node; 25k warps saturates chip) ----
    gather128_k<false><<<cdiv(NN1 * 32, TB), TB>>>(rowptr, cnt, ep, CB1, T1, 768, 0,
                                                   T1, 1.f, 128, 0, NN1);
    gather128_k<true><<<cdiv(NN1 * 32, TB), TB>>>(rowptr, cnt, ep, CB1, T1, 768, 128,
                                                  T1, 2.f, 256, 0, NN1);
    gather128_k<true><<<cdiv(NN1 * 32, TB), TB>>>(rowptr, cnt, ep, CB1, T1, 768, 256,
                                                  T1, 2.f, 384, 128, NN1);
    gather128_k<true><<<cdiv(NN1 * 32, TB), TB>>>(rowptr, cnt, ep, CB1, T1, 768, 384,
                                                  T1, 2.f, 512, 256, NN1);
    gather128_k<true><<<cdiv(NN1 * 32, TB), TB>>>(rowptr, cnt, ep, CB1, T1, 768, 512,
                                                  T1, 2.f, 640, 384, NN1);
    {
        dim3 grid(1, cdiv(NN1, 64));
        gemm_tf32_k<true><<<grid, 256>>>(T1, W1, b1, h1, NN1, 128, 768);
    }

    // ---- pool 1 -> T2 col0 + layer 2 (two half-warps per node) ----
    {
        int g2 = cdiv(NN2 * 2 * 32, TB);
        gather128h_k<false><<<g2, TB>>>(rowptr, cnt, ep, CBD1, h1, 128, 0,
                                        T2, 1.f, 0, 0, NN2);
        gather128h_k<false><<<g2, TB>>>(rowptr, cnt, ep, CB2, T2, 768, 0,
                                        T2, 1.f, 128, 0, NN2);
        gather128h_k<true><<<g2, TB>>>(rowptr, cnt, ep, CB2, T2, 768, 128,
                                       T2, 2.f, 256, 0, NN2);
        gather128h_k<true><<<g2, TB>>>(rowptr, cnt, ep, CB2, T2, 768, 256,
                                       T2, 2.f, 384, 128, NN2);
        gather128h_k<true><<<g2, TB>>>(rowptr, cnt, ep, CB2, T2, 768, 384,
                                       T2, 2.f, 512, 256, NN2);
        gather128h_k<true><<<g2, TB>>>(rowptr, cnt, ep, CB2, T2, 768, 512,
                                       T2, 2.f, 640, 384, NN2);
    }
    {
        dim3 grid(2, cdiv(NN2, 64));
        gemm_tf32_k<false><<<grid, 256>>>(T2, W2, b2, h2, NN2, 256, 768);
    }

    // ---- final linear ----
    final_k<<<1184, 256>>>(h2, linW, out);
}